// round 1
// baseline (speedup 1.0000x reference)
#include <cuda_runtime.h>

#define NH 6
#define HD 32
#define NTOK 64
#define HIDDEN 512
#define TBL 225
#define HW 65536
#define SS_STRIDE 68

// device-global scratch (no allocations allowed)
__device__ float g_bt[TBL * NH];
__device__ float g_hscale[NH];
__device__ float g_bias[NH * NTOK * NTOK];

// ---------------------------------------------------------------------------
// Kernel 0a: continuous-position-bias MLP (225 coords x (2->512->6)) + head scales
// ---------------------------------------------------------------------------
__global__ void bias_mlp_kernel(const float* __restrict__ table,
                                const float* __restrict__ logit_scale,
                                const float* __restrict__ w1,
                                const float* __restrict__ b1,
                                const float* __restrict__ w2) {
    int tid = threadIdx.x;
    if (tid < NH) {
        const float LOGIT_MAX = 4.605170185988091368f; // log(100)
        g_hscale[tid] = expf(fminf(logit_scale[tid], LOGIT_MAX)) * rsqrtf((float)HD);
    }
    if (tid < TBL) {
        float t0 = table[tid * 2 + 0];
        float t1 = table[tid * 2 + 1];
        float acc[NH];
#pragma unroll
        for (int h = 0; h < NH; h++) acc[h] = 0.f;
        for (int j = 0; j < HIDDEN; j++) {
            float hv = fmaf(t1, w1[HIDDEN + j], b1[j]);
            hv = fmaf(t0, w1[j], hv);
            hv = fmaxf(hv, 0.f);
#pragma unroll
            for (int h = 0; h < NH; h++) acc[h] = fmaf(hv, w2[j * NH + h], acc[h]);
        }
#pragma unroll
        for (int h = 0; h < NH; h++) g_bt[tid * NH + h] = acc[h];
    }
}

// ---------------------------------------------------------------------------
// Kernel 0b: gather bias via relative-position index, apply 16*sigmoid
// g_bias layout: [h][n][m]
// ---------------------------------------------------------------------------
__global__ void bias_gather_kernel(const int* __restrict__ index) {
    int gid = blockIdx.x * blockDim.x + threadIdx.x;
    if (gid >= NH * NTOK * NTOK) return;
    int h = gid >> 12;          // / 4096
    int nm = gid & 4095;
    int r = index[nm];
    float bv = g_bt[r * NH + h];
    g_bias[gid] = 16.f / (1.f + expf(-bv));
}

// ---------------------------------------------------------------------------
// Main kernel: one CTA per (window, head). 256 threads.
//   smem: qT/kT/vT as [d][n] (32x64 each), S as [n][m] stride 68.
// ---------------------------------------------------------------------------
__global__ void __launch_bounds__(256) win_attn_kernel(
    const float* __restrict__ qkv,
    const float* __restrict__ mask,
    float* __restrict__ out)
{
    __shared__ float sq[HD * NTOK];
    __shared__ float sk[HD * NTOK];
    __shared__ float sv[HD * NTOK];
    __shared__ float ss[NTOK * SS_STRIDE];
    __shared__ float srinv[NTOK];

    const int tid = threadIdx.x;
    const int bid = blockIdx.x;
    const int h = bid % NH;
    const int b_ = bid / NH;           // 0..2047
    const int b = b_ >> 10;            // batch
    const int w = b_ & 1023;           // window id within image
    const int wy = w >> 5, wx = w & 31;
    // roll(-4,-4): window pixel (i,j) <- original ((wy*8+i+4)&255, (wx*8+j+4)&255)
    const int y0 = wy * 8 + 4;
    const int x0 = wx * 8 + 4;

    // global channel base: channel = t*384 + b*192 + h*32 + d   (qkv is (3,B,192,H,W))
    const int chbase = b * 192 + h * 32;

    // ---- load q,k,v: 1536 float4 loads, transposed into smem [d][n] ----
#pragma unroll
    for (int k4 = 0; k4 < 6; k4++) {
        int idx4 = tid + k4 * 256;
        int t = idx4 >> 9;              // 0..2 (constant per unrolled iter)
        int d = (idx4 >> 4) & 31;
        int q16 = idx4 & 15;            // 16 float4 per (t,d) plane
        int i = q16 >> 1;               // window row 0..7
        int j0 = (q16 & 1) << 2;        // 0 or 4
        int y = (y0 + i) & 255;
        int x = (x0 + j0) & 255;        // 4-aligned, never splits across wrap
        const float4 val = *(const float4*)(qkv + (chbase + t * 384 + d) * HW + y * 256 + x);
        float* dst = (t == 0 ? sq : (t == 1 ? sk : sv)) + d * 64 + i * 8 + j0;
        *(float4*)dst = val;
    }
    __syncthreads();

    const float scale = g_hscale[h];
    const float* bias_h = g_bias + h * 4096;
    const float* mask_w = mask + w * 4096;

    // ---- phase 1: S[n][m] = scale * q.k + bias + mask  (4x4 register tiles) ----
    {
        const int m0 = (tid & 15) * 4;
        const int n0 = (tid >> 4) * 4;
        float acc[4][4];
#pragma unroll
        for (int a = 0; a < 4; a++)
#pragma unroll
            for (int c = 0; c < 4; c++) acc[a][c] = 0.f;

#pragma unroll 8
        for (int d = 0; d < 32; d++) {
            float4 qa = *(const float4*)&sq[d * 64 + n0];
            float4 kb = *(const float4*)&sk[d * 64 + m0];
            float qv[4] = {qa.x, qa.y, qa.z, qa.w};
            float kv[4] = {kb.x, kb.y, kb.z, kb.w};
#pragma unroll
            for (int a = 0; a < 4; a++)
#pragma unroll
                for (int c = 0; c < 4; c++) acc[a][c] = fmaf(qv[a], kv[c], acc[a][c]);
        }
#pragma unroll
        for (int a = 0; a < 4; a++) {
            int n = n0 + a;
            float4 bv = *(const float4*)(bias_h + n * 64 + m0);
            float4 mv = *(const float4*)(mask_w + n * 64 + m0);
            float4 so;
            so.x = fmaf(acc[a][0], scale, bv.x + mv.x);
            so.y = fmaf(acc[a][1], scale, bv.y + mv.y);
            so.z = fmaf(acc[a][2], scale, bv.z + mv.z);
            so.w = fmaf(acc[a][3], scale, bv.w + mv.w);
            *(float4*)&ss[n * SS_STRIDE + m0] = so;
        }
    }
    __syncthreads();

    // ---- phase 2: row softmax (4 threads per row, shfl reduce) ----
    {
        const int row = tid >> 2;
        const int l4 = tid & 3;
        float vals[16];
        float mx = -1e30f;
#pragma unroll
        for (int k = 0; k < 16; k++) {
            vals[k] = ss[row * SS_STRIDE + l4 + k * 4];
            mx = fmaxf(mx, vals[k]);
        }
        mx = fmaxf(mx, __shfl_xor_sync(0xffffffffu, mx, 1));
        mx = fmaxf(mx, __shfl_xor_sync(0xffffffffu, mx, 2));
        float sum = 0.f;
#pragma unroll
        for (int k = 0; k < 16; k++) {
            float e = __expf(vals[k] - mx);
            ss[row * SS_STRIDE + l4 + k * 4] = e;
            sum += e;
        }
        sum += __shfl_xor_sync(0xffffffffu, sum, 1);
        sum += __shfl_xor_sync(0xffffffffu, sum, 2);
        if (l4 == 0) srinv[row] = 1.f / sum;
    }
    __syncthreads();

    // ---- phase 3: O[n][d] = (P @ V) * rinv[n], coalesced float4 stores ----
    {
        const int n0 = (tid & 15) * 4;   // token tile
        const int d0 = (tid >> 4) * 2;   // head-dim tile
        float acc[4][2];
#pragma unroll
        for (int a = 0; a < 4; a++) { acc[a][0] = 0.f; acc[a][1] = 0.f; }

#pragma unroll 4
        for (int m4 = 0; m4 < 16; m4++) {
            int m = m4 * 4;
            float4 v0 = *(const float4*)&sv[d0 * 64 + m];
            float4 v1 = *(const float4*)&sv[(d0 + 1) * 64 + m];
#pragma unroll
            for (int a = 0; a < 4; a++) {
                float4 p = *(const float4*)&ss[(n0 + a) * SS_STRIDE + m];
                acc[a][0] = fmaf(p.x, v0.x, acc[a][0]);
                acc[a][0] = fmaf(p.y, v0.y, acc[a][0]);
                acc[a][0] = fmaf(p.z, v0.z, acc[a][0]);
                acc[a][0] = fmaf(p.w, v0.w, acc[a][0]);
                acc[a][1] = fmaf(p.x, v1.x, acc[a][1]);
                acc[a][1] = fmaf(p.y, v1.y, acc[a][1]);
                acc[a][1] = fmaf(p.z, v1.z, acc[a][1]);
                acc[a][1] = fmaf(p.w, v1.w, acc[a][1]);
            }
        }

        // n0..n0+3 share one window row i (n0 % 8 in {0,4}); roll-back cancels.
        const int i2 = n0 >> 3;
        const int j0s = n0 & 7;
        const int y = (y0 + i2) & 255;
        const int xs = (x0 + j0s) & 255;  // 4-aligned, contiguous (no wrap split)
        const float r0 = srinv[n0], r1 = srinv[n0 + 1],
                    r2 = srinv[n0 + 2], r3 = srinv[n0 + 3];
        float4 o0 = make_float4(acc[0][0] * r0, acc[1][0] * r1, acc[2][0] * r2, acc[3][0] * r3);
        float4 o1 = make_float4(acc[0][1] * r0, acc[1][1] * r1, acc[2][1] * r2, acc[3][1] * r3);
        *(float4*)(out + (chbase + d0) * HW + y * 256 + xs) = o0;
        *(float4*)(out + (chbase + d0 + 1) * HW + y * 256 + xs) = o1;
    }
}

// ---------------------------------------------------------------------------
extern "C" void kernel_launch(void* const* d_in, const int* in_sizes, int n_in,
                              void* d_out, int out_size) {
    const float* qkv         = (const float*)d_in[0];
    const float* table       = (const float*)d_in[1];
    const int*   index       = (const int*)  d_in[2];
    const float* mask        = (const float*)d_in[3];
    const float* logit_scale = (const float*)d_in[4];
    const float* w1          = (const float*)d_in[5];
    const float* b1          = (const float*)d_in[6];
    const float* w2          = (const float*)d_in[7];
    float* out = (float*)d_out;

    bias_mlp_kernel<<<1, 256>>>(table, logit_scale, w1, b1, w2);
    bias_gather_kernel<<<24, 1024>>>(index);
    win_attn_kernel<<<2 * 1024 * NH, 256>>>(qkv, mask, out);
    (void)in_sizes; (void)n_in; (void)out_size;
}

// round 2
// speedup vs baseline: 1.0261x; 1.0261x over previous
#include <cuda_runtime.h>

#define NH 6
#define HD 32
#define NTOK 64
#define HIDDEN 512
#define TBL 225
#define HW 65536
#define SS_STRIDE 68

// device-global scratch (no allocations allowed)
__device__ float g_bt[TBL * NH];
__device__ float g_hscale[NH];
__device__ float g_bias[NH * NTOK * NTOK];

// ---------------------------------------------------------------------------
// Kernel 0a: CPB MLP, parallelized: one block per table row (225 blocks).
// ---------------------------------------------------------------------------
__global__ void __launch_bounds__(128) bias_mlp_kernel(
    const float* __restrict__ table,
    const float* __restrict__ logit_scale,
    const float* __restrict__ w1,
    const float* __restrict__ b1,
    const float* __restrict__ w2) {
    const int row = blockIdx.x;
    const int tid = threadIdx.x;

    if (row == 0 && tid < NH) {
        const float LOGIT_MAX = 4.605170185988091368f; // log(100)
        g_hscale[tid] = expf(fminf(logit_scale[tid], LOGIT_MAX)) * rsqrtf((float)HD);
    }

    const float t0 = table[row * 2 + 0];
    const float t1 = table[row * 2 + 1];
    float acc[NH];
#pragma unroll
    for (int h = 0; h < NH; h++) acc[h] = 0.f;

    for (int j = tid; j < HIDDEN; j += 128) {
        float hv = fmaf(t0, w1[j], fmaf(t1, w1[HIDDEN + j], b1[j]));
        hv = fmaxf(hv, 0.f);
#pragma unroll
        for (int h = 0; h < NH; h++) acc[h] = fmaf(hv, w2[j * NH + h], acc[h]);
    }

    // reduce across 128 threads
#pragma unroll
    for (int h = 0; h < NH; h++) {
#pragma unroll
        for (int o = 16; o > 0; o >>= 1)
            acc[h] += __shfl_xor_sync(0xffffffffu, acc[h], o);
    }
    __shared__ float red[4][NH];
    const int warp = tid >> 5;
    if ((tid & 31) == 0) {
#pragma unroll
        for (int h = 0; h < NH; h++) red[warp][h] = acc[h];
    }
    __syncthreads();
    if (tid == 0) {
#pragma unroll
        for (int h = 0; h < NH; h++)
            g_bt[row * NH + h] = red[0][h] + red[1][h] + red[2][h] + red[3][h];
    }
}

// ---------------------------------------------------------------------------
// Kernel 0b: gather bias via relative-position index, apply 16*sigmoid
// ---------------------------------------------------------------------------
__global__ void bias_gather_kernel(const int* __restrict__ index) {
    int gid = blockIdx.x * blockDim.x + threadIdx.x;
    if (gid >= NH * NTOK * NTOK) return;
    int h = gid >> 12;
    int nm = gid & 4095;
    int r = index[nm];
    float bv = g_bt[r * NH + h];
    g_bias[gid] = 16.f / (1.f + expf(-bv));
}

// ---------------------------------------------------------------------------
// Main kernel: one CTA per (window, head). 128 threads, 3 CTAs/SM.
//  Phase 1: 4n x 8m tiles (1.5 B smem/FMA) -> register softmax via shfl.
//  Phase 3: 4d x 4n tiles over all m (broadcast-heavy LDS).
// ---------------------------------------------------------------------------
__global__ void __launch_bounds__(128) win_attn_kernel(
    const float* __restrict__ qkv,
    const float* __restrict__ mask,
    float* __restrict__ out)
{
    __shared__ __align__(16) float sq[HD * NTOK];
    __shared__ __align__(16) float sk[HD * NTOK];
    __shared__ __align__(16) float sv[HD * NTOK];
    __shared__ __align__(16) float ss[NTOK * SS_STRIDE];

    const int tid = threadIdx.x;
    const int bid = blockIdx.x;
    const int h = bid % NH;
    const int b_ = bid / NH;           // 0..2047
    const int b = b_ >> 10;            // batch
    const int w = b_ & 1023;           // window id within image
    const int wy = w >> 5, wx = w & 31;
    // roll(-4,-4): window pixel (i,j) <- original ((wy*8+i+4)&255, (wx*8+j+4)&255)
    const int y0 = wy * 8 + 4;
    const int x0 = wx * 8 + 4;

    // channel = t*384 + b*192 + h*32 + d   (qkv is (3,B,192,H,W))
    const int chbase = b * 192 + h * 32;

    // ---- load q,k,v: 1536 float4 loads (12/thread), into smem [d][n] ----
#pragma unroll
    for (int k4 = 0; k4 < 12; k4++) {
        int idx4 = tid + k4 * 128;
        int t = idx4 >> 9;              // 0..2 (constant per unrolled iter)
        int d = (idx4 >> 4) & 31;
        int q16 = idx4 & 15;            // 16 float4 per (t,d) plane
        int i = q16 >> 1;               // window row 0..7
        int j0 = (q16 & 1) << 2;        // 0 or 4
        int y = (y0 + i) & 255;
        int x = (x0 + j0) & 255;        // 4-aligned, never splits across wrap
        const float4 val = *(const float4*)(qkv + (chbase + t * 384 + d) * HW + y * 256 + x);
        float* dst = (t == 0 ? sq : (t == 1 ? sk : sv)) + d * 64 + i * 8 + j0;
        *(float4*)dst = val;
    }
    __syncthreads();

    const float scale = g_hscale[h];
    const float* bias_h = g_bias + h * 4096;
    const float* mask_w = mask + w * 4096;

    // ---- phase 1: S = scale*q.k + bias + mask, tiles 4n x 8m ----
    {
        const int mt = tid & 7;
        const int nt = tid >> 3;        // 0..15
        const int m0 = mt * 8;
        const int n0 = nt * 4;
        float acc[4][8];
#pragma unroll
        for (int a = 0; a < 4; a++)
#pragma unroll
            for (int c = 0; c < 8; c++) acc[a][c] = 0.f;

#pragma unroll 8
        for (int d = 0; d < 32; d++) {
            float4 qa = *(const float4*)&sq[d * 64 + n0];
            float4 kb0 = *(const float4*)&sk[d * 64 + m0];
            float4 kb1 = *(const float4*)&sk[d * 64 + m0 + 4];
            float qv[4] = {qa.x, qa.y, qa.z, qa.w};
            float kv[8] = {kb0.x, kb0.y, kb0.z, kb0.w, kb1.x, kb1.y, kb1.z, kb1.w};
#pragma unroll
            for (int a = 0; a < 4; a++)
#pragma unroll
                for (int c = 0; c < 8; c++) acc[a][c] = fmaf(qv[a], kv[c], acc[a][c]);
        }

        // epilogue + register softmax (row = 8 consecutive lanes, shfl 1/2/4)
#pragma unroll
        for (int a = 0; a < 4; a++) {
            const int n = n0 + a;
            float4 bv0 = *(const float4*)(bias_h + n * 64 + m0);
            float4 bv1 = *(const float4*)(bias_h + n * 64 + m0 + 4);
            float4 mv0 = *(const float4*)(mask_w + n * 64 + m0);
            float4 mv1 = *(const float4*)(mask_w + n * 64 + m0 + 4);
            float bm[8] = {bv0.x + mv0.x, bv0.y + mv0.y, bv0.z + mv0.z, bv0.w + mv0.w,
                           bv1.x + mv1.x, bv1.y + mv1.y, bv1.z + mv1.z, bv1.w + mv1.w};
            float s[8];
            float mx = -1e30f;
#pragma unroll
            for (int c = 0; c < 8; c++) {
                s[c] = fmaf(acc[a][c], scale, bm[c]);
                mx = fmaxf(mx, s[c]);
            }
            mx = fmaxf(mx, __shfl_xor_sync(0xffffffffu, mx, 1));
            mx = fmaxf(mx, __shfl_xor_sync(0xffffffffu, mx, 2));
            mx = fmaxf(mx, __shfl_xor_sync(0xffffffffu, mx, 4));
            float sum = 0.f;
#pragma unroll
            for (int c = 0; c < 8; c++) {
                s[c] = __expf(s[c] - mx);
                sum += s[c];
            }
            sum += __shfl_xor_sync(0xffffffffu, sum, 1);
            sum += __shfl_xor_sync(0xffffffffu, sum, 2);
            sum += __shfl_xor_sync(0xffffffffu, sum, 4);
            const float rinv = 1.f / sum;
            float4 p0 = make_float4(s[0] * rinv, s[1] * rinv, s[2] * rinv, s[3] * rinv);
            float4 p1 = make_float4(s[4] * rinv, s[5] * rinv, s[6] * rinv, s[7] * rinv);
            *(float4*)&ss[n * SS_STRIDE + m0] = p0;
            *(float4*)&ss[n * SS_STRIDE + m0 + 4] = p1;
        }
    }
    __syncthreads();

    // ---- phase 3: O[d][n] = V[d][:] . P[n][:]^T, tiles 4d x 4n ----
    {
        const int dt = tid & 7;         // 0..7 -> d0
        const int nt2 = tid >> 3;       // 0..15 -> n0
        const int d0 = dt * 4;
        const int n0 = nt2 * 4;
        float o[4][4];
#pragma unroll
        for (int i = 0; i < 4; i++)
#pragma unroll
            for (int j = 0; j < 4; j++) o[i][j] = 0.f;

#pragma unroll 4
        for (int mb = 0; mb < 16; mb++) {
            const int m = mb * 4;
            float4 p0 = *(const float4*)&ss[(n0 + 0) * SS_STRIDE + m];
            float4 p1 = *(const float4*)&ss[(n0 + 1) * SS_STRIDE + m];
            float4 p2 = *(const float4*)&ss[(n0 + 2) * SS_STRIDE + m];
            float4 p3 = *(const float4*)&ss[(n0 + 3) * SS_STRIDE + m];
            float4 pj[4] = {p0, p1, p2, p3};
#pragma unroll
            for (int i = 0; i < 4; i++) {
                float4 vv = *(const float4*)&sv[(d0 + i) * 64 + m];
#pragma unroll
                for (int j = 0; j < 4; j++) {
                    o[i][j] = fmaf(pj[j].x, vv.x, o[i][j]);
                    o[i][j] = fmaf(pj[j].y, vv.y, o[i][j]);
                    o[i][j] = fmaf(pj[j].z, vv.z, o[i][j]);
                    o[i][j] = fmaf(pj[j].w, vv.w, o[i][j]);
                }
            }
        }

        // store: n0..n0+3 lie in one window row (n0 % 8 in {0,4}); roll cancels.
        const int i2 = n0 >> 3;
        const int j0s = n0 & 7;
        const int y = (y0 + i2) & 255;
        const int xs = (x0 + j0s) & 255;   // 4-aligned, contiguous
#pragma unroll
        for (int i = 0; i < 4; i++) {
            float4 ov = make_float4(o[i][0], o[i][1], o[i][2], o[i][3]);
            *(float4*)(out + (chbase + d0 + i) * HW + y * 256 + xs) = ov;
        }
    }
}

// ---------------------------------------------------------------------------
extern "C" void kernel_launch(void* const* d_in, const int* in_sizes, int n_in,
                              void* d_out, int out_size) {
    const float* qkv         = (const float*)d_in[0];
    const float* table       = (const float*)d_in[1];
    const int*   index       = (const int*)  d_in[2];
    const float* mask        = (const float*)d_in[3];
    const float* logit_scale = (const float*)d_in[4];
    const float* w1          = (const float*)d_in[5];
    const float* b1          = (const float*)d_in[6];
    const float* w2          = (const float*)d_in[7];
    float* out = (float*)d_out;

    // maximize smem carveout so 3 CTAs (41KB each) fit per SM (idempotent)
    cudaFuncSetAttribute(win_attn_kernel,
                         cudaFuncAttributePreferredSharedMemoryCarveout, 100);

    bias_mlp_kernel<<<TBL, 128>>>(table, logit_scale, w1, b1, w2);
    bias_gather_kernel<<<96, 256>>>(index);
    win_attn_kernel<<<2 * 1024 * NH, 128>>>(qkv, mask, out);
    (void)in_sizes; (void)n_in; (void)out_size;
}

// round 3
// speedup vs baseline: 1.3329x; 1.2990x over previous
#include <cuda_runtime.h>

#define NH 6
#define HD 32
#define NTOK 64
#define HIDDEN 512
#define TBL 225
#define HW 65536
#define ST 68

typedef unsigned long long ull;

// packed fp32x2 ops (Blackwell; ptxas never auto-emits these)
#define FMA2(d, a, b, c) \
    asm("fma.rn.f32x2 %0, %1, %2, %3;" : "=l"(d) : "l"(a), "l"(b), "l"(c))
#define PACK2(d, x) \
    asm("mov.b64 %0, {%1, %1};" : "=l"(d) : "f"(x))
#define UNPACK2(lo, hi, v) \
    asm("mov.b64 {%0, %1}, %2;" : "=f"(lo), "=f"(hi) : "l"(v))

union F4U {
    float4 f4;
    float f[4];
    ull u[2];
};

// device-global scratch (no allocations allowed)
__device__ float g_bt[TBL * NH];
__device__ float g_hscale[NH];

// ---------------------------------------------------------------------------
// Kernel 0: CPB MLP, one block per table row (225 blocks) + head scales.
// ---------------------------------------------------------------------------
__global__ void __launch_bounds__(128) bias_mlp_kernel(
    const float* __restrict__ table,
    const float* __restrict__ logit_scale,
    const float* __restrict__ w1,
    const float* __restrict__ b1,
    const float* __restrict__ w2) {
    const int row = blockIdx.x;
    const int tid = threadIdx.x;

    if (row == 0 && tid < NH) {
        const float LOGIT_MAX = 4.605170185988091368f; // log(100)
        g_hscale[tid] = expf(fminf(logit_scale[tid], LOGIT_MAX)) * rsqrtf((float)HD);
    }

    const float t0 = table[row * 2 + 0];
    const float t1 = table[row * 2 + 1];
    float acc[NH];
#pragma unroll
    for (int h = 0; h < NH; h++) acc[h] = 0.f;

    for (int j = tid; j < HIDDEN; j += 128) {
        float hv = fmaf(t0, w1[j], fmaf(t1, w1[HIDDEN + j], b1[j]));
        hv = fmaxf(hv, 0.f);
#pragma unroll
        for (int h = 0; h < NH; h++) acc[h] = fmaf(hv, w2[j * NH + h], acc[h]);
    }

#pragma unroll
    for (int h = 0; h < NH; h++) {
#pragma unroll
        for (int o = 16; o > 0; o >>= 1)
            acc[h] += __shfl_xor_sync(0xffffffffu, acc[h], o);
    }
    __shared__ float red[4][NH];
    const int warp = tid >> 5;
    if ((tid & 31) == 0) {
#pragma unroll
        for (int h = 0; h < NH; h++) red[warp][h] = acc[h];
    }
    __syncthreads();
    if (tid == 0) {
#pragma unroll
        for (int h = 0; h < NH; h++)
            g_bt[row * NH + h] = red[0][h] + red[1][h] + red[2][h] + red[3][h];
    }
}

// ---------------------------------------------------------------------------
// Main kernel: one CTA per (window, head). 128 threads, 5 CTAs/SM.
//  f32x2 packed FMA in both GEMMs; stride-68 smem (2-way max conflicts);
//  bias gather fused (per-head 16*sigmoid table in smem).
// ---------------------------------------------------------------------------
__global__ void __launch_bounds__(128, 5) win_attn_kernel(
    const float* __restrict__ qkv,
    const float* __restrict__ mask,
    const int* __restrict__ index,
    float* __restrict__ out)
{
    __shared__ __align__(16) float sq[HD * ST];
    __shared__ __align__(16) float sk[HD * ST];
    __shared__ __align__(16) float sv[HD * ST];
    __shared__ __align__(16) float ss[NTOK * ST];
    __shared__ float sbt[TBL];

    const int tid = threadIdx.x;
    const int bid = blockIdx.x;
    const int h = bid % NH;
    const int b_ = bid / NH;           // 0..2047
    const int b = b_ >> 10;            // batch
    const int w = b_ & 1023;           // window id within image
    const int wy = w >> 5, wx = w & 31;
    // roll(-4,-4): window pixel (i,j) <- original ((wy*8+i+4)&255, (wx*8+j+4)&255)
    const int y0 = wy * 8 + 4;
    const int x0 = wx * 8 + 4;

    // channel = t*384 + b*192 + h*32 + d   (qkv is (3,B,192,H,W))
    const int chbase = b * 192 + h * 32;

    // ---- per-head bias table: 16*sigmoid(bt[r][h]) -> smem ----
    for (int r = tid; r < TBL; r += 128) {
        float bv = g_bt[r * NH + h];
        sbt[r] = 16.f / (1.f + __expf(-bv));
    }

    // ---- load q,k,v: 1536 float4 loads (12/thread), into smem [d][n] ----
#pragma unroll
    for (int k4 = 0; k4 < 12; k4++) {
        int idx4 = tid + k4 * 128;
        int t = idx4 >> 9;              // 0..2 (constant per unrolled iter)
        int d = (idx4 >> 4) & 31;
        int q16 = idx4 & 15;            // 16 float4 per (t,d) plane
        int i = q16 >> 1;               // window row 0..7
        int j0 = (q16 & 1) << 2;        // 0 or 4
        int y = (y0 + i) & 255;
        int x = (x0 + j0) & 255;        // 4-aligned, never splits across wrap
        const float4 val = *(const float4*)(qkv + (chbase + t * 384 + d) * HW + y * 256 + x);
        float* dst = (t == 0 ? sq : (t == 1 ? sk : sv)) + d * ST + i * 8 + j0;
        *(float4*)dst = val;
    }
    __syncthreads();

    const float scale = g_hscale[h];
    const float* mask_w = mask + w * 4096;

    // ---- phase 1: S = scale*q.k + bias + mask, tiles 4n x 8m, f32x2 over m ----
    {
        const int m0 = (tid & 7) * 8;
        const int n0 = (tid >> 3) * 4;
        ull acc2[4][4];
        const ull z = 0ull;
#pragma unroll
        for (int a = 0; a < 4; a++)
#pragma unroll
            for (int c = 0; c < 4; c++) acc2[a][c] = z;

        const float* pq = sq + n0;
        const float* pk = sk + m0;
#pragma unroll 4
        for (int d = 0; d < 32; d++) {
            F4U qa, kb0, kb1;
            qa.f4  = *(const float4*)(pq + d * ST);
            kb0.f4 = *(const float4*)(pk + d * ST);
            kb1.f4 = *(const float4*)(pk + d * ST + 4);
#pragma unroll
            for (int a = 0; a < 4; a++) {
                ull qp;
                PACK2(qp, qa.f[a]);
                FMA2(acc2[a][0], qp, kb0.u[0], acc2[a][0]);
                FMA2(acc2[a][1], qp, kb0.u[1], acc2[a][1]);
                FMA2(acc2[a][2], qp, kb1.u[0], acc2[a][2]);
                FMA2(acc2[a][3], qp, kb1.u[1], acc2[a][3]);
            }
        }

        // epilogue: bias gather + mask + register softmax (row = 8 lanes)
#pragma unroll
        for (int a = 0; a < 4; a++) {
            const int n = n0 + a;
            float4 mv0 = *(const float4*)(mask_w + n * 64 + m0);
            float4 mv1 = *(const float4*)(mask_w + n * 64 + m0 + 4);
            int4 iv0 = *(const int4*)(index + n * 64 + m0);
            int4 iv1 = *(const int4*)(index + n * 64 + m0 + 4);
            float bm[8];
            bm[0] = sbt[iv0.x] + mv0.x;  bm[1] = sbt[iv0.y] + mv0.y;
            bm[2] = sbt[iv0.z] + mv0.z;  bm[3] = sbt[iv0.w] + mv0.w;
            bm[4] = sbt[iv1.x] + mv1.x;  bm[5] = sbt[iv1.y] + mv1.y;
            bm[6] = sbt[iv1.z] + mv1.z;  bm[7] = sbt[iv1.w] + mv1.w;

            float s[8];
#pragma unroll
            for (int c = 0; c < 4; c++) {
                float lo, hi;
                UNPACK2(lo, hi, acc2[a][c]);
                s[2 * c]     = fmaf(lo, scale, bm[2 * c]);
                s[2 * c + 1] = fmaf(hi, scale, bm[2 * c + 1]);
            }
            float mx = -1e30f;
#pragma unroll
            for (int c = 0; c < 8; c++) mx = fmaxf(mx, s[c]);
            mx = fmaxf(mx, __shfl_xor_sync(0xffffffffu, mx, 1));
            mx = fmaxf(mx, __shfl_xor_sync(0xffffffffu, mx, 2));
            mx = fmaxf(mx, __shfl_xor_sync(0xffffffffu, mx, 4));
            float sum = 0.f;
#pragma unroll
            for (int c = 0; c < 8; c++) {
                s[c] = __expf(s[c] - mx);
                sum += s[c];
            }
            sum += __shfl_xor_sync(0xffffffffu, sum, 1);
            sum += __shfl_xor_sync(0xffffffffu, sum, 2);
            sum += __shfl_xor_sync(0xffffffffu, sum, 4);
            const float rinv = 1.f / sum;
            float4 p0 = make_float4(s[0] * rinv, s[1] * rinv, s[2] * rinv, s[3] * rinv);
            float4 p1 = make_float4(s[4] * rinv, s[5] * rinv, s[6] * rinv, s[7] * rinv);
            *(float4*)&ss[n * ST + m0] = p0;
            *(float4*)&ss[n * ST + m0 + 4] = p1;
        }
    }
    __syncthreads();

    // ---- phase 3: O[d][n] = V[d][:] . P[n][:]^T, tiles 4d x 4n, f32x2 over m ----
    {
        const int d0 = (tid & 7) * 4;
        const int n0 = (tid >> 3) * 4;
        ull o2[4][4];
        const ull z = 0ull;
#pragma unroll
        for (int i = 0; i < 4; i++)
#pragma unroll
            for (int j = 0; j < 4; j++) o2[i][j] = z;

        const float* pv = sv + d0 * ST;
        const float* pp = ss + n0 * ST;
#pragma unroll 4
        for (int mb = 0; mb < 16; mb++) {
            const int m = mb * 4;
            F4U p[4], v[4];
#pragma unroll
            for (int j = 0; j < 4; j++) p[j].f4 = *(const float4*)(pp + j * ST + m);
#pragma unroll
            for (int i = 0; i < 4; i++) v[i].f4 = *(const float4*)(pv + i * ST + m);
#pragma unroll
            for (int i = 0; i < 4; i++)
#pragma unroll
                for (int j = 0; j < 4; j++) {
                    FMA2(o2[i][j], v[i].u[0], p[j].u[0], o2[i][j]);
                    FMA2(o2[i][j], v[i].u[1], p[j].u[1], o2[i][j]);
                }
        }

        // store: n0..n0+3 lie in one window row (n0 % 8 in {0,4}); roll cancels.
        const int i2 = n0 >> 3;
        const int j0s = n0 & 7;
        const int y = (y0 + i2) & 255;
        const int xs = (x0 + j0s) & 255;   // 4-aligned, contiguous
#pragma unroll
        for (int i = 0; i < 4; i++) {
            float ov[4];
#pragma unroll
            for (int j = 0; j < 4; j++) {
                float lo, hi;
                UNPACK2(lo, hi, o2[i][j]);
                ov[j] = lo + hi;
            }
            *(float4*)(out + (chbase + d0 + i) * HW + y * 256 + xs) =
                make_float4(ov[0], ov[1], ov[2], ov[3]);
        }
    }
}

// ---------------------------------------------------------------------------
extern "C" void kernel_launch(void* const* d_in, const int* in_sizes, int n_in,
                              void* d_out, int out_size) {
    const float* qkv         = (const float*)d_in[0];
    const float* table       = (const float*)d_in[1];
    const int*   index       = (const int*)  d_in[2];
    const float* mask        = (const float*)d_in[3];
    const float* logit_scale = (const float*)d_in[4];
    const float* w1          = (const float*)d_in[5];
    const float* b1          = (const float*)d_in[6];
    const float* w2          = (const float*)d_in[7];
    float* out = (float*)d_out;

    cudaFuncSetAttribute(win_attn_kernel,
                         cudaFuncAttributePreferredSharedMemoryCarveout, 100);

    bias_mlp_kernel<<<TBL, 128>>>(table, logit_scale, w1, b1, w2);
    win_attn_kernel<<<2 * 1024 * NH, 128>>>(qkv, mask, index, out);
    (void)in_sizes; (void)n_in; (void)out_size;
}

// round 4
// speedup vs baseline: 1.9540x; 1.4659x over previous
#include <cuda_runtime.h>

#define NH 6
#define HD 32
#define NTOK 64
#define HIDDEN 512
#define TBL 225
#define HW 65536
#define ST 68

typedef unsigned long long ull;

// packed fp32x2 ops (Blackwell; ptxas never auto-emits these)
#define FMA2(d, a, b, c) \
    asm("fma.rn.f32x2 %0, %1, %2, %3;" : "=l"(d) : "l"(a), "l"(b), "l"(c))
#define PACK2(d, x) \
    asm("mov.b64 %0, {%1, %1};" : "=l"(d) : "f"(x))
#define UNPACK2(lo, hi, v) \
    asm("mov.b64 {%0, %1}, %2;" : "=f"(lo), "=f"(hi) : "l"(v))

union F4U {
    float4 f4;
    float f[4];
    ull u[2];
};

// device-global scratch (no allocations allowed)
__device__ float g_bt[TBL * NH];
__device__ float g_hscale[NH];
__device__ float g_bias[NH * NTOK * NTOK];

// ---------------------------------------------------------------------------
// Kernel 0a: CPB MLP, one block per table row (225 blocks) + head scales.
// ---------------------------------------------------------------------------
__global__ void __launch_bounds__(128) bias_mlp_kernel(
    const float* __restrict__ table,
    const float* __restrict__ logit_scale,
    const float* __restrict__ w1,
    const float* __restrict__ b1,
    const float* __restrict__ w2) {
    const int row = blockIdx.x;
    const int tid = threadIdx.x;

    if (row == 0 && tid < NH) {
        const float LOGIT_MAX = 4.605170185988091368f; // log(100)
        g_hscale[tid] = expf(fminf(logit_scale[tid], LOGIT_MAX)) * rsqrtf((float)HD);
    }

    const float t0 = table[row * 2 + 0];
    const float t1 = table[row * 2 + 1];
    float acc[NH];
#pragma unroll
    for (int h = 0; h < NH; h++) acc[h] = 0.f;

    for (int j = tid; j < HIDDEN; j += 128) {
        float hv = fmaf(t0, w1[j], fmaf(t1, w1[HIDDEN + j], b1[j]));
        hv = fmaxf(hv, 0.f);
#pragma unroll
        for (int h = 0; h < NH; h++) acc[h] = fmaf(hv, w2[j * NH + h], acc[h]);
    }

#pragma unroll
    for (int h = 0; h < NH; h++) {
#pragma unroll
        for (int o = 16; o > 0; o >>= 1)
            acc[h] += __shfl_xor_sync(0xffffffffu, acc[h], o);
    }
    __shared__ float red[4][NH];
    const int warp = tid >> 5;
    if ((tid & 31) == 0) {
#pragma unroll
        for (int h = 0; h < NH; h++) red[warp][h] = acc[h];
    }
    __syncthreads();
    if (tid == 0) {
#pragma unroll
        for (int h = 0; h < NH; h++)
            g_bt[row * NH + h] = red[0][h] + red[1][h] + red[2][h] + red[3][h];
    }
}

// ---------------------------------------------------------------------------
// Kernel 0b: expand bias -> g_bias[h][n][m] = 16*sigmoid(bt[index[n][m]][h])
// ---------------------------------------------------------------------------
__global__ void bias_gather_kernel(const int* __restrict__ index) {
    int gid = blockIdx.x * blockDim.x + threadIdx.x;
    if (gid >= NH * NTOK * NTOK) return;
    int h = gid >> 12;
    int nm = gid & 4095;
    int r = index[nm];
    float bv = g_bt[r * NH + h];
    g_bias[gid] = 16.f / (1.f + __expf(-bv));
}

// ---------------------------------------------------------------------------
// Main kernel: one CTA per (window, head). 128 threads, 5 CTAs/SM.
//  All smem accesses bank-conflict-free; f32x2 FMAs; precomputed bias table.
// ---------------------------------------------------------------------------
__global__ void __launch_bounds__(128, 5) win_attn_kernel(
    const float* __restrict__ qkv,
    const float* __restrict__ mask,
    const float* __restrict__ bias,
    float* __restrict__ out)
{
    __shared__ __align__(16) float sq[HD * ST];
    __shared__ __align__(16) float sk[HD * ST];
    __shared__ __align__(16) float sv[HD * ST];
    __shared__ __align__(16) float ss[NTOK * ST];

    const int tid = threadIdx.x;
    const int bid = blockIdx.x;
    const int h = bid % NH;
    const int b_ = bid / NH;           // 0..2047
    const int b = b_ >> 10;            // batch
    const int w = b_ & 1023;           // window id within image
    const int wy = w >> 5, wx = w & 31;
    // roll(-4,-4): window pixel (i,j) <- original ((wy*8+i+4)&255, (wx*8+j+4)&255)
    const int y0 = wy * 8 + 4;
    const int x0 = wx * 8 + 4;

    // channel = t*384 + b*192 + h*32 + d   (qkv is (3,B,192,H,W))
    const int chbase = b * 192 + h * 32;

    // ---- load q,k,v: 1536 float4 loads (12/thread), into smem [d][n] ----
#pragma unroll
    for (int k4 = 0; k4 < 12; k4++) {
        int idx4 = tid + k4 * 128;
        int t = idx4 >> 9;              // 0..2 (constant per unrolled iter)
        int d = (idx4 >> 4) & 31;
        int q16 = idx4 & 15;            // 16 float4 per (t,d) plane
        int i = q16 >> 1;               // window row 0..7
        int j0 = (q16 & 1) << 2;        // 0 or 4
        int y = (y0 + i) & 255;
        int x = (x0 + j0) & 255;        // 4-aligned, never splits across wrap
        const float4 val = *(const float4*)(qkv + (chbase + t * 384 + d) * HW + y * 256 + x);
        float* dst = (t == 0 ? sq : (t == 1 ? sk : sv)) + d * ST + i * 8 + j0;
        *(float4*)dst = val;
    }
    __syncthreads();

    const float scale = g_hscale[h];
    const float* mask_w = mask + w * 4096;
    const float* bias_h = bias + h * 4096;

    // ---- phase 1: S = scale*q.k + bias + mask ----
    // thread tile: 4 n-rows x 8 m-cols, m set = {m0..m0+3} U {m0+32..m0+35},
    // m0 = (tid&7)*4 -> all K loads hit 8 distinct bank groups (conflict-free).
    {
        const int m0 = (tid & 7) * 4;
        const int n0 = (tid >> 3) * 4;
        ull acc2[4][4];
#pragma unroll
        for (int a = 0; a < 4; a++)
#pragma unroll
            for (int c = 0; c < 4; c++) acc2[a][c] = 0ull;

        const float* pq = sq + n0;
        const float* pk = sk + m0;
#pragma unroll 4
        for (int d = 0; d < 32; d++) {
            F4U qa, kb0, kb1;
            qa.f4  = *(const float4*)(pq + d * ST);
            kb0.f4 = *(const float4*)(pk + d * ST);
            kb1.f4 = *(const float4*)(pk + d * ST + 32);
#pragma unroll
            for (int a = 0; a < 4; a++) {
                ull qp;
                PACK2(qp, qa.f[a]);
                FMA2(acc2[a][0], qp, kb0.u[0], acc2[a][0]);
                FMA2(acc2[a][1], qp, kb0.u[1], acc2[a][1]);
                FMA2(acc2[a][2], qp, kb1.u[0], acc2[a][2]);
                FMA2(acc2[a][3], qp, kb1.u[1], acc2[a][3]);
            }
        }

        // epilogue: bias + mask + register softmax (row = 8 lanes, shfl 1/2/4)
#pragma unroll
        for (int a = 0; a < 4; a++) {
            const int n = n0 + a;
            float4 mv0 = *(const float4*)(mask_w + n * 64 + m0);
            float4 mv1 = *(const float4*)(mask_w + n * 64 + m0 + 32);
            float4 bv0 = *(const float4*)(bias_h + n * 64 + m0);
            float4 bv1 = *(const float4*)(bias_h + n * 64 + m0 + 32);
            float bm[8] = {bv0.x + mv0.x, bv0.y + mv0.y, bv0.z + mv0.z, bv0.w + mv0.w,
                           bv1.x + mv1.x, bv1.y + mv1.y, bv1.z + mv1.z, bv1.w + mv1.w};
            float s[8];
#pragma unroll
            for (int c = 0; c < 4; c++) {
                float lo, hi;
                UNPACK2(lo, hi, acc2[a][c]);
                s[2 * c]     = fmaf(lo, scale, bm[2 * c]);
                s[2 * c + 1] = fmaf(hi, scale, bm[2 * c + 1]);
            }
            float mx = -1e30f;
#pragma unroll
            for (int c = 0; c < 8; c++) mx = fmaxf(mx, s[c]);
            mx = fmaxf(mx, __shfl_xor_sync(0xffffffffu, mx, 1));
            mx = fmaxf(mx, __shfl_xor_sync(0xffffffffu, mx, 2));
            mx = fmaxf(mx, __shfl_xor_sync(0xffffffffu, mx, 4));
            float sum = 0.f;
#pragma unroll
            for (int c = 0; c < 8; c++) {
                s[c] = __expf(s[c] - mx);
                sum += s[c];
            }
            sum += __shfl_xor_sync(0xffffffffu, sum, 1);
            sum += __shfl_xor_sync(0xffffffffu, sum, 2);
            sum += __shfl_xor_sync(0xffffffffu, sum, 4);
            const float rinv = 1.f / sum;
            float4 p0 = make_float4(s[0] * rinv, s[1] * rinv, s[2] * rinv, s[3] * rinv);
            float4 p1 = make_float4(s[4] * rinv, s[5] * rinv, s[6] * rinv, s[7] * rinv);
            *(float4*)&ss[n * ST + m0] = p0;
            *(float4*)&ss[n * ST + m0 + 32] = p1;
        }
    }
    __syncthreads();

    // ---- phase 3: O[d][n] = V[d][:] . P[n][:]^T ----
    // thread tile: d in {d0, d0+8, d0+16, d0+24} (d0 = tid&7) x 4 n-cols
    // -> V loads hit 8 distinct bank groups (conflict-free).
    {
        const int d0 = tid & 7;
        const int n0 = (tid >> 3) * 4;
        ull o2[4][4];
#pragma unroll
        for (int i = 0; i < 4; i++)
#pragma unroll
            for (int j = 0; j < 4; j++) o2[i][j] = 0ull;

        const float* pv = sv + d0 * ST;
        const float* pp = ss + n0 * ST;
#pragma unroll 4
        for (int mb = 0; mb < 16; mb++) {
            const int m = mb * 4;
            F4U p[4], v[4];
#pragma unroll
            for (int j = 0; j < 4; j++) p[j].f4 = *(const float4*)(pp + j * ST + m);
#pragma unroll
            for (int i = 0; i < 4; i++) v[i].f4 = *(const float4*)(pv + i * 8 * ST + m);
#pragma unroll
            for (int i = 0; i < 4; i++)
#pragma unroll
                for (int j = 0; j < 4; j++) {
                    FMA2(o2[i][j], v[i].u[0], p[j].u[0], o2[i][j]);
                    FMA2(o2[i][j], v[i].u[1], p[j].u[1], o2[i][j]);
                }
        }

        // store: n0..n0+3 lie in one window row (n0 % 8 in {0,4}); roll cancels.
        const int i2 = n0 >> 3;
        const int j0s = n0 & 7;
        const int y = (y0 + i2) & 255;
        const int xs = (x0 + j0s) & 255;   // 4-aligned, contiguous
#pragma unroll
        for (int i = 0; i < 4; i++) {
            float ov[4];
#pragma unroll
            for (int j = 0; j < 4; j++) {
                float lo, hi;
                UNPACK2(lo, hi, o2[i][j]);
                ov[j] = lo + hi;
            }
            *(float4*)(out + (chbase + d0 + i * 8) * HW + y * 256 + xs) =
                make_float4(ov[0], ov[1], ov[2], ov[3]);
        }
    }
}

// ---------------------------------------------------------------------------
extern "C" void kernel_launch(void* const* d_in, const int* in_sizes, int n_in,
                              void* d_out, int out_size) {
    const float* qkv         = (const float*)d_in[0];
    const float* table       = (const float*)d_in[1];
    const int*   index       = (const int*)  d_in[2];
    const float* mask        = (const float*)d_in[3];
    const float* logit_scale = (const float*)d_in[4];
    const float* w1          = (const float*)d_in[5];
    const float* b1          = (const float*)d_in[6];
    const float* w2          = (const float*)d_in[7];
    float* out = (float*)d_out;

    cudaFuncSetAttribute(win_attn_kernel,
                         cudaFuncAttributePreferredSharedMemoryCarveout, 100);

    bias_mlp_kernel<<<TBL, 128>>>(table, logit_scale, w1, b1, w2);
    bias_gather_kernel<<<96, 256>>>(index);

    // g_bias address via symbol (resolved at compile time into the kernel):
    float* d_bias = nullptr;
    cudaGetSymbolAddress((void**)&d_bias, g_bias);
    win_attn_kernel<<<2 * 1024 * NH, 128>>>(qkv, mask, d_bias, out);
    (void)in_sizes; (void)n_in; (void)out_size;
}